// round 3
// baseline (speedup 1.0000x reference)
#include <cuda_runtime.h>
#include <math.h>

#define NUM_CLASSES 10000
#define FEATURE_DIM 512
#define BATCH_MAX   16384

// Scratch: __device__ globals (no allocation allowed in kernel_launch).
__device__ int   g_count[NUM_CLASSES];
__device__ float g_loss;

// ---------------------------------------------------------------------------
// K1: zero the per-class counts and the loss accumulator.
// ---------------------------------------------------------------------------
__global__ void zero_kernel() {
    int i = blockIdx.x * blockDim.x + threadIdx.x;
    if (i < NUM_CLASSES) g_count[i] = 0;
    if (i == 0) g_loss = 0.0f;
}

// ---------------------------------------------------------------------------
// K2: per-class histogram of labels.
// ---------------------------------------------------------------------------
__global__ void hist_kernel(const int* __restrict__ label, int batch) {
    int i = blockIdx.x * blockDim.x + threadIdx.x;
    if (i < batch) {
        atomicAdd(&g_count[label[i]], 1);
    }
}

// ---------------------------------------------------------------------------
// K3: one warp per sample. Compute ||feat_i - centers[label_i]||, divide by
// per-class count, block-reduce, one atomicAdd per block.
// FEATURE_DIM=512 floats = 128 float4; each lane handles 4 float4 per operand.
// ---------------------------------------------------------------------------
__global__ void __launch_bounds__(256) dist_kernel(
    const float* __restrict__ feat,
    const int*   __restrict__ label,
    const float* __restrict__ centers,
    int batch)
{
    const int warp_global = (blockIdx.x * blockDim.x + threadIdx.x) >> 5;
    const int lane        = threadIdx.x & 31;
    const int warp_local  = threadIdx.x >> 5;

    float contrib = 0.0f;

    if (warp_global < batch) {
        const int lbl = label[warp_global];

        const float4* __restrict__ f =
            reinterpret_cast<const float4*>(feat + (size_t)warp_global * FEATURE_DIM);
        const float4* __restrict__ c =
            reinterpret_cast<const float4*>(centers + (size_t)lbl * FEATURE_DIM);

        float acc = 0.0f;
        #pragma unroll
        for (int j = 0; j < FEATURE_DIM / 4 / 32; j++) {   // 4 iterations
            float4 a = f[lane + j * 32];
            float4 b = __ldg(&c[lane + j * 32]);
            float dx = a.x - b.x;
            float dy = a.y - b.y;
            float dz = a.z - b.z;
            float dw = a.w - b.w;
            acc = fmaf(dx, dx, acc);
            acc = fmaf(dy, dy, acc);
            acc = fmaf(dz, dz, acc);
            acc = fmaf(dw, dw, acc);
        }

        // warp tree reduction
        #pragma unroll
        for (int o = 16; o > 0; o >>= 1)
            acc += __shfl_xor_sync(0xffffffffu, acc, o);

        if (lane == 0) {
            float num = (float)g_count[lbl];   // >= 1 (label counts itself)
            contrib = sqrtf(acc) / num;
        }
    }

    // block reduction over 8 warps (only lane 0 of each warp contributes)
    __shared__ float s[8];
    if (lane == 0) s[warp_local] = contrib;
    __syncthreads();
    if (threadIdx.x == 0) {
        float sum = 0.0f;
        #pragma unroll
        for (int k = 0; k < 8; k++) sum += s[k];
        atomicAdd(&g_loss, sum);
    }
}

// ---------------------------------------------------------------------------
// K4: finalize — divide by batch and write the scalar output.
// ---------------------------------------------------------------------------
__global__ void final_kernel(float* __restrict__ out, float inv_batch) {
    out[0] = g_loss * inv_batch;
}

// ---------------------------------------------------------------------------
// launch
// ---------------------------------------------------------------------------
extern "C" void kernel_launch(void* const* d_in, const int* in_sizes, int n_in,
                              void* d_out, int out_size)
{
    const float* feat    = (const float*)d_in[0];
    const int*   label   = (const int*)d_in[1];
    const float* centers = (const float*)d_in[2];
    float*       out     = (float*)d_out;

    const int batch = in_sizes[1];             // 16384

    // K1: zero scratch
    {
        int threads = 256;
        int blocks  = (NUM_CLASSES + threads - 1) / threads;
        zero_kernel<<<blocks, threads>>>();
    }
    // K2: histogram
    {
        int threads = 256;
        int blocks  = (batch + threads - 1) / threads;
        hist_kernel<<<blocks, threads>>>(label, batch);
    }
    // K3: distances + weighted sum (one warp per sample, 8 warps/block)
    {
        int threads = 256;
        int warps_per_block = threads / 32;
        int blocks = (batch + warps_per_block - 1) / warps_per_block;
        dist_kernel<<<blocks, threads>>>(feat, label, centers, batch);
    }
    // K4: finalize
    final_kernel<<<1, 1>>>(out, 1.0f / (float)batch);
}